// round 2
// baseline (speedup 1.0000x reference)
#include <cuda_runtime.h>
#include <cstdint>
#include <cfloat>

// Problem constants
#define F 4096      // nb_features
#define C 64        // coord dim
#define B 1024      // batch
#define K 16        // nb_neighbors
#define J (F*K + 1) // 65537 gathered columns

// Scratch (no allocations allowed)
__device__ float g_sq[F];
__device__ int   g_cols[J];

__device__ __forceinline__ unsigned long long fma2(unsigned long long a,
                                                   unsigned long long b,
                                                   unsigned long long c) {
    unsigned long long d;
    asm("fma.rn.f32x2 %0, %1, %2, %3;" : "=l"(d) : "l"(a), "l"(b), "l"(c));
    return d;
}

__device__ __forceinline__ bool lexlt(float d, int g, float v, int i) {
    return (d < v) || (d == v && g < i);
}

// ---------------------------------------------------------------------------
// Kernel 1: per-feature squared norms  sq[f] = sum_c coord[c][f]^2
// Sequential, UNFUSED mul+add to match XLA-CPU square+reduce emission
// (no FMA contraction in the reference's elementwise/reduce loop).
// ---------------------------------------------------------------------------
__global__ __launch_bounds__(256) void k_sq(const float* __restrict__ coord) {
    int f = blockIdx.x * 256 + threadIdx.x;
    float s = 0.f;
#pragma unroll
    for (int c = 0; c < C; ++c) {
        float x = coord[c * F + f];
        s = __fadd_rn(s, __fmul_rn(x, x));
    }
    g_sq[f] = s;
}

// ---------------------------------------------------------------------------
// Kernel 2: distances + top-16 per feature row -> g_cols
//   CTA: 256 threads = 32 rows x 8 slots. Each slot scans 512 g's.
//   g tiles of 256 staged in SMEM; f vectors + sq staged in SMEM.
//   Dot product: sequential fp32 FMA chain over c=0..63 (matches Eigen gebp /
//   cublas sgemm accumulation order).
// ---------------------------------------------------------------------------
#define ROWS 32
#define SLOTS 8
#define TG 256
#define NTILES (F / TG)   // 16

// dynamic smem layout (in floats)
#define OFF_SG   0                       // 64 x 256          = 16384
#define OFF_SF   (OFF_SG + C * TG)       // 64 x 32           = 2048
#define OFF_SSQ  (OFF_SF + C * ROWS)     // 256
#define OFF_MV   (OFF_SSQ + TG)          // 32 x 129          = 4128
#define OFF_MI   (OFF_MV + ROWS * 129)   // 32 x 129 (ints)   = 4128
#define SMEM2_FLOATS (OFF_MI + ROWS * 129)
#define SMEM2_BYTES  (SMEM2_FLOATS * 4)

__global__ __launch_bounds__(256) void k_disttopk(const float* __restrict__ coord) {
    extern __shared__ float smem[];
    float* s_g  = smem + OFF_SG;
    float* s_f  = smem + OFF_SF;
    float* s_sq = smem + OFF_SSQ;
    float* s_mv = smem + OFF_MV;
    int*   s_mi = (int*)(smem + OFF_MI);

    const int tid  = threadIdx.x;
    const int row  = tid >> 3;   // 0..31
    const int slot = tid & 7;    // 0..7
    const int f0   = blockIdx.x * ROWS;

    // stage f-vectors: s_f[c*32 + r] = coord[c][f0+r]
    for (int idx = tid; idx < C * ROWS; idx += 256) {
        int c = idx >> 5, r = idx & 31;
        s_f[idx] = coord[c * F + f0 + r];
    }

    const float sqf = g_sq[f0 + row];

    // local top-16 (registers, constant indexing only)
    float vv[K];
    int   ii[K];
#pragma unroll
    for (int j = 0; j < K; ++j) { vv[j] = FLT_MAX; ii[j] = 0x7FFFFFFF; }

    for (int t = 0; t < NTILES; ++t) {
        const int gbase = t * TG;
        __syncthreads();
        // stage g tile: s_g[c*256 + i] = coord[c][gbase+i]
        for (int idx = tid; idx < (C * TG) / 4; idx += 256) {
            int c = idx >> 6, q = idx & 63;
            *(float4*)(s_g + c * TG + q * 4) =
                *(const float4*)(coord + c * F + gbase + q * 4);
        }
        if (tid < TG / 4) {
            *(float4*)(s_sq + tid * 4) = *(const float4*)(g_sq + gbase + tid * 4);
        }
        __syncthreads();

        // accumulate dots: thread covers g = gbase + m*32 + slot*4 + {0..3}
        unsigned long long acc[16];
#pragma unroll
        for (int p = 0; p < 16; ++p) acc[p] = 0ull;

#pragma unroll 4
        for (int c = 0; c < C; ++c) {
            float a = s_f[c * ROWS + row];
            unsigned int au = __float_as_uint(a);
            unsigned long long a2;
            asm("mov.b64 %0, {%1, %1};" : "=l"(a2) : "r"(au));
            const float* base = s_g + c * TG + slot * 4;
#pragma unroll
            for (int m = 0; m < 8; ++m) {
                ulonglong2 bb = *(const ulonglong2*)(base + m * 32);
                acc[2 * m]     = fma2(a2, bb.x, acc[2 * m]);
                acc[2 * m + 1] = fma2(a2, bb.y, acc[2 * m + 1]);
            }
        }

        // finalize distances + top-k update (ascending g within thread)
        // d2 = ((-2*dot) + sq_g) + sq_f ; -2*dot is exact, so fmaf(-2,dot,sqg)
        // rounds identically to the reference's ((-2*dot)+sq_j).
#pragma unroll
        for (int m = 0; m < 8; ++m) {
#pragma unroll
            for (int e = 0; e < 4; ++e) {
                unsigned long long a = acc[2 * m + (e >> 1)];
                float dot = __uint_as_float((e & 1) ? (unsigned)(a >> 32) : (unsigned)a);
                int go = m * 32 + slot * 4 + e;
                float sqg = s_sq[go];
                float d2 = __fadd_rn(fmaf(-2.f, dot, sqg), sqf);
                float d  = sqrtf(fmaxf(d2, 0.f));
                int g = gbase + go;
                if (lexlt(d, g, vv[K - 1], ii[K - 1])) {
                    float cv = d; int ci = g;
#pragma unroll
                    for (int j = 0; j < K; ++j) {
                        bool sw = lexlt(cv, ci, vv[j], ii[j]);
                        float tv = vv[j]; int ti = ii[j];
                        if (sw) { vv[j] = cv; ii[j] = ci; cv = tv; ci = ti; }
                    }
                }
            }
        }
    }

    // dump sorted lists to smem, then 8-way merge per row
    {
        int mb = row * 129 + slot * K;
#pragma unroll
        for (int j = 0; j < K; ++j) { s_mv[mb + j] = vv[j]; s_mi[mb + j] = ii[j]; }
    }
    __syncthreads();

    if (tid < ROWS) {
        int f = f0 + tid;
        int mb = tid * 129;
        int h[SLOTS];
#pragma unroll
        for (int s = 0; s < SLOTS; ++s) h[s] = 0;
        for (int k = 0; k < K; ++k) {
            float bv = FLT_MAX; int bi = 0x7FFFFFFF; int bs = 0;
            bool any = false;
#pragma unroll
            for (int s = 0; s < SLOTS; ++s) {
                if (h[s] < K) {
                    float v = s_mv[mb + s * K + h[s]];
                    int   i = s_mi[mb + s * K + h[s]];
                    if (!any || lexlt(v, i, bv, bi)) { bv = v; bi = i; bs = s; any = true; }
                }
            }
            g_cols[1 + f * K + k] = bi;
            h[bs]++;
        }
    }
    if (blockIdx.x == 0 && tid == 0) g_cols[0] = 0;
}

// ---------------------------------------------------------------------------
// Kernel 3: gather. CTA caches 8 input rows (128 KB SMEM), streams all J cols.
// ---------------------------------------------------------------------------
#define RB 8
#define GATHER_SMEM (RB * F * 4)

__global__ __launch_bounds__(256) void k_gather(const float* __restrict__ inputs,
                                                float* __restrict__ out) {
    extern __shared__ float s_in[];   // RB * 4096
    const int b0 = blockIdx.x * RB;

    for (int idx = threadIdx.x; idx < (RB * F) / 4; idx += 256) {
        int r = idx >> 10, q = idx & 1023;
        *(float4*)(s_in + r * F + q * 4) =
            *(const float4*)(inputs + (size_t)(b0 + r) * F + q * 4);
    }
    __syncthreads();

    for (int j = threadIdx.x; j < J; j += 256) {
        int c = __ldg(&g_cols[j]);
#pragma unroll
        for (int r = 0; r < RB; ++r) {
            out[(size_t)(b0 + r) * J + j] = s_in[r * F + c];
        }
    }
}

// ---------------------------------------------------------------------------
extern "C" void kernel_launch(void* const* d_in, const int* in_sizes, int n_in,
                              void* d_out, int out_size) {
    const float* inputs = (const float*)d_in[0];
    const float* coord  = (const float*)d_in[1];
    // defensive: inputs has 4,194,304 elems, coordinates 262,144
    if (n_in >= 2 && in_sizes[0] < in_sizes[1]) {
        const float* t = inputs; inputs = coord; coord = t;
    }
    float* out = (float*)d_out;

    static bool attr_done = false;
    if (!attr_done) {
        cudaFuncSetAttribute(k_disttopk, cudaFuncAttributeMaxDynamicSharedMemorySize,
                             SMEM2_BYTES);
        cudaFuncSetAttribute(k_gather, cudaFuncAttributeMaxDynamicSharedMemorySize,
                             GATHER_SMEM);
        attr_done = true;
    }

    k_sq<<<F / 256, 256>>>(coord);
    k_disttopk<<<F / ROWS, 256, SMEM2_BYTES>>>(coord);
    k_gather<<<B / RB, 256, GATHER_SMEM>>>(inputs, out);
}

// round 3
// speedup vs baseline: 1.3128x; 1.3128x over previous
#include <cuda_runtime.h>
#include <cstdint>
#include <cfloat>

// Problem constants
#define F 4096      // nb_features
#define C 64        // coord dim
#define B 1024      // batch
#define K 16        // nb_neighbors
#define J (F*K + 1) // 65537 gathered columns

// Scratch (no allocations allowed)
__device__ float g_sq[F];
__device__ int   g_cols[J];
__device__ float g_pd[2 * F * K];   // partial top-k distances (2 g-halves)
__device__ int   g_pi[2 * F * K];   // partial top-k indices

__device__ __forceinline__ unsigned long long fma2(unsigned long long a,
                                                   unsigned long long b,
                                                   unsigned long long c) {
    unsigned long long d;
    asm("fma.rn.f32x2 %0, %1, %2, %3;" : "=l"(d) : "l"(a), "l"(b), "l"(c));
    return d;
}
__device__ __forceinline__ float lo32(unsigned long long v) {
    return __uint_as_float((unsigned)v);
}
__device__ __forceinline__ float hi32(unsigned long long v) {
    return __uint_as_float((unsigned)(v >> 32));
}
__device__ __forceinline__ bool lexlt(float d, int g, float v, int i) {
    return (d < v) || (d == v && g < i);
}

// ---------------------------------------------------------------------------
// Kernel 1: per-feature squared norms (UNFUSED mul+add, sequential — matches
// the reference's square+reduce rounding; this made rel_err exactly 0).
// ---------------------------------------------------------------------------
__global__ __launch_bounds__(256) void k_sq(const float* __restrict__ coord) {
    int f = blockIdx.x * 256 + threadIdx.x;
    float s = 0.f;
#pragma unroll
    for (int c = 0; c < C; ++c) {
        float x = coord[c * F + f];
        s = __fadd_rn(s, __fmul_rn(x, x));
    }
    g_sq[f] = s;
}

// ---------------------------------------------------------------------------
// Kernel 2: register-blocked distance GEMM + fused top-16.
//   Grid: 64 row-tiles x 2 g-halves = 128 CTAs, 256 threads.
//   CTA tile: 64 rows x 2048 g, inner g tiles of 256.
//   Thread micro-tile: 8 rows x 8 g (1 B LDS per MAC -> FMA-pipe bound).
// ---------------------------------------------------------------------------
#define ROWS_CTA 64
#define GHALF    2048
#define TGG      256
#define NTL      (GHALF / TGG)   // 8
#define DPITCH   260             // s_d row pitch (floats)

// smem layout (floats)
#define OFF_F    0                          // 64c x 64r      = 4096
#define OFF_SQF  (OFF_F + C * ROWS_CTA)     // 64
#define OFF_G    (OFF_SQF + ROWS_CTA)       // 64c x 256g     = 16384
#define OFF_SQG  (OFF_G + C * TGG)          // 256
#define OFF_D    (OFF_SQG + TGG)            // 64 x 260       = 16640
#define SMEM_D_FLOATS (OFF_D + ROWS_CTA * DPITCH)
#define SMEM_D_BYTES  (SMEM_D_FLOATS * 4)   // 149760 B

__global__ __launch_bounds__(256, 1) void k_dist(const float* __restrict__ coord) {
    extern __shared__ float sm[];
    float* s_f   = sm + OFF_F;
    float* s_sqf = sm + OFF_SQF;
    float* s_g   = sm + OFF_G;
    float* s_sqg = sm + OFF_SQG;
    float* s_d   = sm + OFF_D;

    const int tid  = threadIdx.x;
    const int tx   = tid & 31;    // g group (compute phase)
    const int ty   = tid >> 5;    // row group = warp id
    const int f0   = (blockIdx.x >> 1) * ROWS_CTA;
    const int half = blockIdx.x & 1;
    const int g0   = half * GHALF;

    // stage f tile: s_f[c*64 + r] = coord[c][f0+r]
    for (int idx = tid; idx < (C * ROWS_CTA) / 4; idx += 256) {
        int c = idx >> 4, r4 = (idx & 15) * 4;
        *(float4*)(s_f + c * ROWS_CTA + r4) = *(const float4*)(coord + c * F + f0 + r4);
    }
    if (tid < ROWS_CTA / 4)
        *(float4*)(s_sqf + tid * 4) = *(const float4*)(g_sq + f0 + tid * 4);

    // top-k scan state: thread = (srow, sq), scans g = sq + 4*i (bank-clean)
    const int srow = tid >> 2, sq = tid & 3;
    float vv[K]; int ii[K];
#pragma unroll
    for (int j = 0; j < K; ++j) { vv[j] = FLT_MAX; ii[j] = 0x7FFFFFFF; }
    float thr2 = FLT_MAX;   // conservative squared threshold (no false negatives)

    for (int t = 0; t < NTL; ++t) {
        const int gb = g0 + t * TGG;
        __syncthreads();   // prev scan done; safe to overwrite s_g/s_d
        for (int idx = tid; idx < (C * TGG) / 4; idx += 256) {
            int c = idx >> 6, o4 = (idx & 63) * 4;
            *(float4*)(s_g + c * TGG + o4) = *(const float4*)(coord + c * F + gb + o4);
        }
        if (tid < TGG / 4)
            *(float4*)(s_sqg + tid * 4) = *(const float4*)(g_sq + gb + tid * 4);
        __syncthreads();

        // ---- compute 8x8 micro-tile: g = tx*4+{0..3} and 128+tx*4+{0..3} ----
        unsigned long long acc[8][4];
#pragma unroll
        for (int r = 0; r < 8; ++r)
#pragma unroll
            for (int p = 0; p < 4; ++p) acc[r][p] = 0ull;

        const float* fp = s_f + ty * 8;
        const float* gp = s_g + tx * 4;
#pragma unroll 4
        for (int c = 0; c < C; ++c) {
            float4 a0 = *(const float4*)(fp + c * ROWS_CTA);
            float4 a1 = *(const float4*)(fp + c * ROWS_CTA + 4);
            ulonglong2 b0 = *(const ulonglong2*)(gp + c * TGG);        // g: tx*4..+3
            ulonglong2 b1 = *(const ulonglong2*)(gp + c * TGG + 128);  // g: 128+tx*4..+3
            float av[8] = {a0.x, a0.y, a0.z, a0.w, a1.x, a1.y, a1.z, a1.w};
#pragma unroll
            for (int r = 0; r < 8; ++r) {
                unsigned long long a2;
                asm("mov.b64 %0,{%1,%1};" : "=l"(a2) : "r"(__float_as_uint(av[r])));
                acc[r][0] = fma2(a2, b0.x, acc[r][0]);
                acc[r][1] = fma2(a2, b0.y, acc[r][1]);
                acc[r][2] = fma2(a2, b1.x, acc[r][2]);
                acc[r][3] = fma2(a2, b1.y, acc[r][3]);
            }
        }

        // ---- finalize d2 and stage to s_d ----
        float sg0[4], sg1[4];
#pragma unroll
        for (int e = 0; e < 4; ++e) {
            sg0[e] = s_sqg[tx * 4 + e];
            sg1[e] = s_sqg[128 + tx * 4 + e];
        }
#pragma unroll
        for (int r = 0; r < 8; ++r) {
            float sf = s_sqf[ty * 8 + r];
            float4 d0, d1;
            d0.x = __fadd_rn(fmaf(-2.f, lo32(acc[r][0]), sg0[0]), sf);
            d0.y = __fadd_rn(fmaf(-2.f, hi32(acc[r][0]), sg0[1]), sf);
            d0.z = __fadd_rn(fmaf(-2.f, lo32(acc[r][1]), sg0[2]), sf);
            d0.w = __fadd_rn(fmaf(-2.f, hi32(acc[r][1]), sg0[3]), sf);
            d1.x = __fadd_rn(fmaf(-2.f, lo32(acc[r][2]), sg1[0]), sf);
            d1.y = __fadd_rn(fmaf(-2.f, hi32(acc[r][2]), sg1[1]), sf);
            d1.z = __fadd_rn(fmaf(-2.f, lo32(acc[r][3]), sg1[2]), sf);
            d1.w = __fadd_rn(fmaf(-2.f, hi32(acc[r][3]), sg1[3]), sf);
            float* drow = s_d + (ty * 8 + r) * DPITCH + tx * 4;
            *(float4*)(drow)       = d0;
            *(float4*)(drow + 128) = d1;
        }
        __syncthreads();

        // ---- top-k scan (prefilter on d2; exact sqrt path on survivors) ----
        const float* dr = s_d + srow * DPITCH;
        for (int i = 0; i < 64; ++i) {
            int go = sq + 4 * i;
            float d2 = dr[go];
            if (d2 <= thr2) {
                float d = sqrtf(fmaxf(d2, 0.f));
                int g = gb + go;
                if (lexlt(d, g, vv[K - 1], ii[K - 1])) {
                    float cv = d; int ci = g;
#pragma unroll
                    for (int j = 0; j < K; ++j) {
                        bool sw = lexlt(cv, ci, vv[j], ii[j]);
                        float tv = vv[j]; int ti = ii[j];
                        if (sw) { vv[j] = cv; ii[j] = ci; cv = tv; ci = ti; }
                    }
                    float v15 = vv[K - 1];
                    thr2 = (v15 >= FLT_MAX) ? FLT_MAX
                         : __uint_as_float(__float_as_uint(__fmul_ru(v15, v15)) + 8);
                }
            }
        }
    }

    // ---- merge 4 per-row lists -> partial top-16 (alias s_d as buffers) ----
    __syncthreads();
    float* s_mv = s_d;                              // [64][68]
    int*   s_mi = (int*)(s_d + ROWS_CTA * 68);      // [64][68]
    {
        int mb = srow * 68 + sq * K;
#pragma unroll
        for (int j = 0; j < K; ++j) { s_mv[mb + j] = vv[j]; s_mi[mb + j] = ii[j]; }
    }
    __syncthreads();

    if (tid < ROWS_CTA) {
        int mb = tid * 68;
        int h[4] = {0, 0, 0, 0};
        int outb = half * F * K + (f0 + tid) * K;
        for (int k = 0; k < K; ++k) {
            float bv = FLT_MAX; int bi = 0x7FFFFFFF; int bs = 0; bool any = false;
#pragma unroll
            for (int s = 0; s < 4; ++s) {
                if (h[s] < K) {
                    float v = s_mv[mb + s * K + h[s]];
                    int   i = s_mi[mb + s * K + h[s]];
                    if (!any || lexlt(v, i, bv, bi)) { bv = v; bi = i; bs = s; any = true; }
                }
            }
            g_pd[outb + k] = bv;
            g_pi[outb + k] = bi;
            h[bs]++;
        }
    }
}

// ---------------------------------------------------------------------------
// Kernel 3: merge the two g-half partial lists per feature -> g_cols
// ---------------------------------------------------------------------------
__global__ __launch_bounds__(256) void k_merge() {
    int f = blockIdx.x * 256 + threadIdx.x;
    int b0 = f * K;
    int b1 = F * K + f * K;
    int p0 = 0, p1 = 0;
    for (int k = 0; k < K; ++k) {
        float v0 = (p0 < K) ? g_pd[b0 + p0] : FLT_MAX;
        int   i0 = (p0 < K) ? g_pi[b0 + p0] : 0x7FFFFFFF;
        float v1 = (p1 < K) ? g_pd[b1 + p1] : FLT_MAX;
        int   i1 = (p1 < K) ? g_pi[b1 + p1] : 0x7FFFFFFF;
        bool take0 = lexlt(v0, i0, v1, i1);
        g_cols[1 + f * K + k] = take0 ? i0 : i1;
        if (take0) p0++; else p1++;
    }
    if (f == 0) g_cols[0] = 0;
}

// ---------------------------------------------------------------------------
// Kernel 4: gather. CTA caches 8 input rows (128 KB SMEM), streams all J cols.
// ---------------------------------------------------------------------------
#define RB 8
#define GATHER_SMEM (RB * F * 4)

__global__ __launch_bounds__(256) void k_gather(const float* __restrict__ inputs,
                                                float* __restrict__ out) {
    extern __shared__ float s_in[];   // RB * 4096
    const int b0 = blockIdx.x * RB;

    for (int idx = threadIdx.x; idx < (RB * F) / 4; idx += 256) {
        int r = idx >> 10, q = idx & 1023;
        *(float4*)(s_in + r * F + q * 4) =
            *(const float4*)(inputs + (size_t)(b0 + r) * F + q * 4);
    }
    __syncthreads();

    for (int j = threadIdx.x; j < J; j += 256) {
        int c = __ldg(&g_cols[j]);
#pragma unroll
        for (int r = 0; r < RB; ++r) {
            out[(size_t)(b0 + r) * J + j] = s_in[r * F + c];
        }
    }
}

// ---------------------------------------------------------------------------
extern "C" void kernel_launch(void* const* d_in, const int* in_sizes, int n_in,
                              void* d_out, int out_size) {
    const float* inputs = (const float*)d_in[0];
    const float* coord  = (const float*)d_in[1];
    if (n_in >= 2 && in_sizes[0] < in_sizes[1]) {
        const float* t = inputs; inputs = coord; coord = t;
    }
    float* out = (float*)d_out;

    static bool attr_done = false;
    if (!attr_done) {
        cudaFuncSetAttribute(k_dist, cudaFuncAttributeMaxDynamicSharedMemorySize,
                             SMEM_D_BYTES);
        cudaFuncSetAttribute(k_gather, cudaFuncAttributeMaxDynamicSharedMemorySize,
                             GATHER_SMEM);
        attr_done = true;
    }

    k_sq<<<F / 256, 256>>>(coord);
    k_dist<<<(F / ROWS_CTA) * 2, 256, SMEM_D_BYTES>>>(coord);
    k_merge<<<F / 256, 256>>>();
    k_gather<<<B / RB, 256, GATHER_SMEM>>>(inputs, out);
}

// round 4
// speedup vs baseline: 1.3433x; 1.0233x over previous
#include <cuda_runtime.h>
#include <cstdint>
#include <cfloat>

// Problem constants
#define F 4096      // nb_features
#define C 64        // coord dim
#define B 1024      // batch
#define K 16        // nb_neighbors
#define J (F*K + 1) // 65537 gathered columns

// Scratch (no allocations allowed)
__device__ float g_sq[F];
__device__ int   g_cols[J];
__device__ float g_pd[2 * F * K];   // partial top-k distances (2 g-halves)
__device__ int   g_pi[2 * F * K];   // partial top-k indices

__device__ __forceinline__ bool lexlt(float d, int g, float v, int i) {
    return (d < v) || (d == v && g < i);
}

// ---------------------------------------------------------------------------
// Kernel 1: per-feature squared norms (UNFUSED mul+add, sequential — matches
// the reference's square+reduce rounding; this made rel_err exactly 0).
// ---------------------------------------------------------------------------
__global__ __launch_bounds__(256) void k_sq(const float* __restrict__ coord) {
    int f = blockIdx.x * 256 + threadIdx.x;
    float s = 0.f;
#pragma unroll
    for (int c = 0; c < C; ++c) {
        float x = coord[c * F + f];
        s = __fadd_rn(s, __fmul_rn(x, x));
    }
    g_sq[f] = s;
}

// ---------------------------------------------------------------------------
// Kernel 2: register-blocked distance GEMM + fused top-16.
//   PLAIN scalar FFMA only (no fma.rn.f32x2 — suspected slow lowering).
//   Grid: 64 row-tiles x 2 g-halves = 128 CTAs, 256 threads.
//   CTA tile: 64 rows x 2048 g, inner g tiles of 256.
//   Thread micro-tile: 8 rows x 8 g. b-loads contiguous, a-loads warp-uniform.
// ---------------------------------------------------------------------------
#define ROWS_CTA 64
#define GHALF    2048
#define TGG      256
#define NTL      (GHALF / TGG)   // 8
#define DPITCH   260             // s_d row pitch (floats)

// smem layout (floats)
#define OFF_F    0                          // 64c x 64r      = 4096
#define OFF_SQF  (OFF_F + C * ROWS_CTA)     // 64
#define OFF_G    (OFF_SQF + ROWS_CTA)       // 64c x 256g     = 16384
#define OFF_SQG  (OFF_G + C * TGG)          // 256
#define OFF_D    (OFF_SQG + TGG)            // 64 x 260       = 16640
#define SMEM_D_FLOATS (OFF_D + ROWS_CTA * DPITCH)
#define SMEM_D_BYTES  (SMEM_D_FLOATS * 4)   // 149760 B

__global__ __launch_bounds__(256, 1) void k_dist(const float* __restrict__ coord) {
    extern __shared__ float sm[];
    float* s_f   = sm + OFF_F;
    float* s_sqf = sm + OFF_SQF;
    float* s_g   = sm + OFF_G;
    float* s_sqg = sm + OFF_SQG;
    float* s_d   = sm + OFF_D;

    const int tid  = threadIdx.x;
    const int tx   = tid & 31;    // g group (warp lane)
    const int ty   = tid >> 5;    // row group = warp id (warp-uniform)
    const int f0   = (blockIdx.x >> 1) * ROWS_CTA;
    const int half = blockIdx.x & 1;
    const int g0   = half * GHALF;

    // stage f tile: s_f[c*64 + r] = coord[c][f0+r]
    for (int idx = tid; idx < (C * ROWS_CTA) / 4; idx += 256) {
        int c = idx >> 4, r4 = (idx & 15) * 4;
        *(float4*)(s_f + c * ROWS_CTA + r4) = *(const float4*)(coord + c * F + f0 + r4);
    }
    if (tid < ROWS_CTA / 4)
        *(float4*)(s_sqf + tid * 4) = *(const float4*)(g_sq + f0 + tid * 4);

    // top-k scan state: thread = (srow, sq), scans g = sq + 4*i (bank-clean)
    const int srow = tid >> 2, sq = tid & 3;
    float vv[K]; int ii[K];
#pragma unroll
    for (int j = 0; j < K; ++j) { vv[j] = FLT_MAX; ii[j] = 0x7FFFFFFF; }
    float thr2 = FLT_MAX;   // conservative squared threshold (no false negatives)

    for (int t = 0; t < NTL; ++t) {
        const int gb = g0 + t * TGG;
        __syncthreads();   // prev scan done; safe to overwrite s_g/s_d
        for (int idx = tid; idx < (C * TGG) / 4; idx += 256) {
            int c = idx >> 6, o4 = (idx & 63) * 4;
            *(float4*)(s_g + c * TGG + o4) = *(const float4*)(coord + c * F + gb + o4);
        }
        if (tid < TGG / 4)
            *(float4*)(s_sqg + tid * 4) = *(const float4*)(g_sq + gb + tid * 4);
        __syncthreads();

        // ---- compute 8x8 micro-tile: g = tx*4+{0..3} and 128+tx*4+{0..3} ----
        float acc[8][8];
#pragma unroll
        for (int r = 0; r < 8; ++r)
#pragma unroll
            for (int e = 0; e < 8; ++e) acc[r][e] = 0.f;

        const float* fp = s_f + ty * 8;
        const float* gp = s_g + tx * 4;
#pragma unroll 4
        for (int c = 0; c < C; ++c) {
            float4 a0 = *(const float4*)(fp + c * ROWS_CTA);
            float4 a1 = *(const float4*)(fp + c * ROWS_CTA + 4);
            float4 b0 = *(const float4*)(gp + c * TGG);        // g: tx*4..+3
            float4 b1 = *(const float4*)(gp + c * TGG + 128);  // g: 128+tx*4..+3
            float av[8] = {a0.x, a0.y, a0.z, a0.w, a1.x, a1.y, a1.z, a1.w};
            float bv[8] = {b0.x, b0.y, b0.z, b0.w, b1.x, b1.y, b1.z, b1.w};
#pragma unroll
            for (int r = 0; r < 8; ++r)
#pragma unroll
                for (int e = 0; e < 8; ++e)
                    acc[r][e] = __fmaf_rn(av[r], bv[e], acc[r][e]);
        }

        // ---- finalize d2 and stage to s_d ----
        float sg[8];
#pragma unroll
        for (int e = 0; e < 4; ++e) {
            sg[e]     = s_sqg[tx * 4 + e];
            sg[4 + e] = s_sqg[128 + tx * 4 + e];
        }
#pragma unroll
        for (int r = 0; r < 8; ++r) {
            float sf = s_sqf[ty * 8 + r];
            float4 d0, d1;
            d0.x = __fadd_rn(__fmaf_rn(-2.f, acc[r][0], sg[0]), sf);
            d0.y = __fadd_rn(__fmaf_rn(-2.f, acc[r][1], sg[1]), sf);
            d0.z = __fadd_rn(__fmaf_rn(-2.f, acc[r][2], sg[2]), sf);
            d0.w = __fadd_rn(__fmaf_rn(-2.f, acc[r][3], sg[3]), sf);
            d1.x = __fadd_rn(__fmaf_rn(-2.f, acc[r][4], sg[4]), sf);
            d1.y = __fadd_rn(__fmaf_rn(-2.f, acc[r][5], sg[5]), sf);
            d1.z = __fadd_rn(__fmaf_rn(-2.f, acc[r][6], sg[6]), sf);
            d1.w = __fadd_rn(__fmaf_rn(-2.f, acc[r][7], sg[7]), sf);
            float* drow = s_d + (ty * 8 + r) * DPITCH + tx * 4;
            *(float4*)(drow)       = d0;
            *(float4*)(drow + 128) = d1;
        }
        __syncthreads();

        // ---- top-k scan (prefilter on d2; exact sqrt path on survivors) ----
        const float* dr = s_d + srow * DPITCH;
        for (int i = 0; i < 64; ++i) {
            int go = sq + 4 * i;
            float d2 = dr[go];
            if (d2 <= thr2) {
                float d = sqrtf(fmaxf(d2, 0.f));
                int g = gb + go;
                if (lexlt(d, g, vv[K - 1], ii[K - 1])) {
                    float cv = d; int ci = g;
#pragma unroll
                    for (int j = 0; j < K; ++j) {
                        bool sw = lexlt(cv, ci, vv[j], ii[j]);
                        float tv = vv[j]; int ti = ii[j];
                        if (sw) { vv[j] = cv; ii[j] = ci; cv = tv; ci = ti; }
                    }
                    float v15 = vv[K - 1];
                    thr2 = (v15 >= FLT_MAX) ? FLT_MAX
                         : __uint_as_float(__float_as_uint(__fmul_ru(v15, v15)) + 8);
                }
            }
        }
    }

    // ---- merge 4 per-row lists -> partial top-16 (alias s_d as buffers) ----
    __syncthreads();
    float* s_mv = s_d;                              // [64][68]
    int*   s_mi = (int*)(s_d + ROWS_CTA * 68);      // [64][68]
    {
        int mb = srow * 68 + sq * K;
#pragma unroll
        for (int j = 0; j < K; ++j) { s_mv[mb + j] = vv[j]; s_mi[mb + j] = ii[j]; }
    }
    __syncthreads();

    if (tid < ROWS_CTA) {
        int mb = tid * 68;
        int h[4] = {0, 0, 0, 0};
        int outb = half * F * K + (f0 + tid) * K;
        for (int k = 0; k < K; ++k) {
            float bv = FLT_MAX; int bi = 0x7FFFFFFF; int bs = 0; bool any = false;
#pragma unroll
            for (int s = 0; s < 4; ++s) {
                if (h[s] < K) {
                    float v = s_mv[mb + s * K + h[s]];
                    int   i = s_mi[mb + s * K + h[s]];
                    if (!any || lexlt(v, i, bv, bi)) { bv = v; bi = i; bs = s; any = true; }
                }
            }
            g_pd[outb + k] = bv;
            g_pi[outb + k] = bi;
            h[bs]++;
        }
    }
}

// ---------------------------------------------------------------------------
// Kernel 3: merge the two g-half partial lists per feature -> g_cols
// ---------------------------------------------------------------------------
__global__ __launch_bounds__(256) void k_merge() {
    int f = blockIdx.x * 256 + threadIdx.x;
    int b0 = f * K;
    int b1 = F * K + f * K;
    int p0 = 0, p1 = 0;
    for (int k = 0; k < K; ++k) {
        float v0 = (p0 < K) ? g_pd[b0 + p0] : FLT_MAX;
        int   i0 = (p0 < K) ? g_pi[b0 + p0] : 0x7FFFFFFF;
        float v1 = (p1 < K) ? g_pd[b1 + p1] : FLT_MAX;
        int   i1 = (p1 < K) ? g_pi[b1 + p1] : 0x7FFFFFFF;
        bool take0 = lexlt(v0, i0, v1, i1);
        g_cols[1 + f * K + k] = take0 ? i0 : i1;
        if (take0) p0++; else p1++;
    }
    if (f == 0) g_cols[0] = 0;
}

// ---------------------------------------------------------------------------
// Kernel 4: gather. CTA caches 4 input rows (64 KB SMEM), streams all J cols.
// Streaming stores (.cs) for the write-once 268 MB output.
// ---------------------------------------------------------------------------
#define RB 4
#define GATHER_SMEM (RB * F * 4)

__global__ __launch_bounds__(256) void k_gather(const float* __restrict__ inputs,
                                                float* __restrict__ out) {
    extern __shared__ float s_in[];   // RB * 4096
    const int b0 = blockIdx.x * RB;

    for (int idx = threadIdx.x; idx < (RB * F) / 4; idx += 256) {
        int r = idx >> 10, q = idx & 1023;
        *(float4*)(s_in + r * F + q * 4) =
            *(const float4*)(inputs + (size_t)(b0 + r) * F + q * 4);
    }
    __syncthreads();

    for (int j = threadIdx.x; j < J; j += 256) {
        int c = __ldg(&g_cols[j]);
#pragma unroll
        for (int r = 0; r < RB; ++r) {
            __stcs(out + (size_t)(b0 + r) * J + j, s_in[r * F + c]);
        }
    }
}

// ---------------------------------------------------------------------------
extern "C" void kernel_launch(void* const* d_in, const int* in_sizes, int n_in,
                              void* d_out, int out_size) {
    const float* inputs = (const float*)d_in[0];
    const float* coord  = (const float*)d_in[1];
    if (n_in >= 2 && in_sizes[0] < in_sizes[1]) {
        const float* t = inputs; inputs = coord; coord = t;
    }
    float* out = (float*)d_out;

    static bool attr_done = false;
    if (!attr_done) {
        cudaFuncSetAttribute(k_dist, cudaFuncAttributeMaxDynamicSharedMemorySize,
                             SMEM_D_BYTES);
        cudaFuncSetAttribute(k_gather, cudaFuncAttributeMaxDynamicSharedMemorySize,
                             GATHER_SMEM);
        attr_done = true;
    }

    k_sq<<<F / 256, 256>>>(coord);
    k_dist<<<(F / ROWS_CTA) * 2, 256, SMEM_D_BYTES>>>(coord);
    k_merge<<<F / 256, 256>>>();
    k_gather<<<B / RB, 256, GATHER_SMEM>>>(inputs, out);
}